// round 13
// baseline (speedup 1.0000x reference)
#include <cuda_runtime.h>

typedef unsigned long long u64;

#define NTHREADS 256
#define F4_PER_THREAD 4
#define EPT (F4_PER_THREAD * 4)
#define PAIRS (EPT / 2)

// ---- constants from the reference (compile-time) ----
#define HCONST { -0.4542235f, 0.7169895f, 0.44056657f, 0.24707365f, \
                 -0.35661384f, 2.5729966f, 4.1841526f, 1.098845f,   \
                 1.553965f, 1.2579314f, 1.1466882f, 1.9164954f,     \
                 2.775174f, 1.2413996f, -3.303845f, 3.1743326f }
#define DCONST { 0.6011055f, 0.32070085f, 0.1728974f, 0.07595864f,  \
                 -0.04305187f, -0.0706069f, -0.02941904f, -0.13304795f, \
                 -0.07925092f, -0.07016345f, 0.39347357f, 0.43960708f,  \
                 -0.01215541f, 0.28329173f, -0.036314f, -0.02618981f }
#define TCONST { 0.7052508f, 0.35964987f, 0.10623224f, -0.04634768f, \
                 0.8112458f, -0.24774243f, -0.44142142f, -1.3476763f, \
                 -0.4575439f, -1.9938357f, 0.99998903f, 0.99853265f,  \
                 0.82849f, 0.57890254f, -2.021475f, -2.7414792f }

// ---- packed f32x2 helpers (Blackwell FFMA2 path, PTX-only) ----
__device__ __forceinline__ u64 pack2(float lo, float hi) {
    u64 r;
    asm("mov.b64 %0, {%1, %2};" : "=l"(r) : "f"(lo), "f"(hi));
    return r;
}
__device__ __forceinline__ void unpack2(u64 p, float& lo, float& hi) {
    asm("mov.b64 {%0, %1}, %2;" : "=f"(lo), "=f"(hi) : "l"(p));
}
__device__ __forceinline__ u64 ffma2(u64 a, u64 b, u64 c) {
    u64 d;
    asm("fma.rn.f32x2 %0, %1, %2, %3;" : "=l"(d) : "l"(a), "l"(b), "l"(c));
    return d;
}
__device__ __forceinline__ u64 fmul2(u64 a, u64 b) {
    u64 d;
    asm("mul.rn.f32x2 %0, %1, %2;" : "=l"(d) : "l"(a), "l"(b));
    return d;
}
// set.gt -> SASS FSET.BF: 1.0f if a > b else 0.0f, single issue, no predicate.
__device__ __forceinline__ float fset_gt(float a, float b) {
    float d;
    asm("set.gt.f32.f32 %0, %1, %2;" : "=f"(d) : "f"(a), "f"(b));
    return d;
}

__global__ void __launch_bounds__(NTHREADS)
spike_f32x2_kernel(const float4* __restrict__ x, float4* __restrict__ out) {
    const float H[16] = HCONST;
    const float D[16] = DCONST;
    const float T[16] = TCONST;

    const int base = blockIdx.x * (NTHREADS * F4_PER_THREAD) + threadIdx.x;

    float vl[PAIRS], vh[PAIRS];
    u64 v2[PAIRS], o2[PAIRS], z2[PAIRS];

#pragma unroll
    for (int j = 0; j < F4_PER_THREAD; j++) {
        float4 t = __ldcs(x + base + j * NTHREADS);
        vl[2 * j]     = t.x; vh[2 * j]     = t.y;
        vl[2 * j + 1] = t.z; vh[2 * j + 1] = t.w;
        v2[2 * j]     = pack2(t.x, t.y);
        v2[2 * j + 1] = pack2(t.z, t.w);
    }

    // step 0: z starts at 0, so no v-update; o = z * d0
    {
        const u64 d2 = pack2(D[0], D[0]);
#pragma unroll
        for (int p = 0; p < PAIRS; p++) {
            float zl = fset_gt(vl[p], T[0]);
            float zh = fset_gt(vh[p], T[0]);
            z2[p] = pack2(zl, zh);
            o2[p] = fmul2(z2[p], d2);
        }
    }

#pragma unroll
    for (int k = 1; k < 16; k++) {
        const u64 nh2 = pack2(-H[k], -H[k]);
        const u64 d2  = pack2(D[k], D[k]);
#pragma unroll
        for (int p = 0; p < PAIRS; p++) {
            // v = fma(z_prev, -h, v)  — bit-identical to v - z*h for z in {0,1}
            v2[p] = ffma2(z2[p], nh2, v2[p]);
            unpack2(v2[p], vl[p], vh[p]);
            float zl = fset_gt(vl[p], T[k]);   // FSET.BF -> 1.0f / 0.0f
            float zh = fset_gt(vh[p], T[k]);
            z2[p] = pack2(zl, zh);
            // out = fma(z, d, out)
            o2[p] = ffma2(z2[p], d2, o2[p]);
        }
    }

#pragma unroll
    for (int j = 0; j < F4_PER_THREAD; j++) {
        float ox, oy, oz, ow;
        unpack2(o2[2 * j], ox, oy);
        unpack2(o2[2 * j + 1], oz, ow);
        __stcs(out + base + j * NTHREADS, make_float4(ox, oy, oz, ow));
    }
}

// Generic scalar fallback (any n); never launched for the bench shape.
__global__ void __launch_bounds__(NTHREADS)
spike_generic_kernel(const float* __restrict__ x, float* __restrict__ out, int n) {
    const float H[16] = HCONST;
    const float D[16] = DCONST;
    const float T[16] = TCONST;
    int idx = blockIdx.x * NTHREADS + threadIdx.x;
    if (idx >= n) return;
    float v = x[idx], o = 0.0f;
    bool z = false;
#pragma unroll
    for (int k = 0; k < 16; k++) {
        if (z) v -= H[k];
        z = v > T[k];
        if (z) o += D[k];
    }
    out[idx] = o;
}

extern "C" void kernel_launch(void* const* d_in, const int* in_sizes, int n_in,
                              void* d_out, int out_size) {
    const float* x = (const float*)d_in[0];
    float* out = (float*)d_out;
    int n = in_sizes[0];

    const int per_block = NTHREADS * EPT;  // elements per block
    if (n % per_block == 0) {
        int blocks = n / per_block;
        spike_f32x2_kernel<<<blocks, NTHREADS>>>((const float4*)x, (float4*)out);
    } else {
        int blocks = (n + NTHREADS - 1) / NTHREADS;
        spike_generic_kernel<<<blocks, NTHREADS>>>(x, out, n);
    }
}

// round 14
// speedup vs baseline: 1.5919x; 1.5919x over previous
#include <cuda_runtime.h>

typedef unsigned long long u64;

#define NTHREADS 256
#define F4_PER_THREAD 4
#define EPT (F4_PER_THREAD * 4)
#define PAIRS (EPT / 2)

// ---- constants from the reference (compile-time) ----
#define HCONST { -0.4542235f, 0.7169895f, 0.44056657f, 0.24707365f, \
                 -0.35661384f, 2.5729966f, 4.1841526f, 1.098845f,   \
                 1.553965f, 1.2579314f, 1.1466882f, 1.9164954f,     \
                 2.775174f, 1.2413996f, -3.303845f, 3.1743326f }
#define DCONST { 0.6011055f, 0.32070085f, 0.1728974f, 0.07595864f,  \
                 -0.04305187f, -0.0706069f, -0.02941904f, -0.13304795f, \
                 -0.07925092f, -0.07016345f, 0.39347357f, 0.43960708f,  \
                 -0.01215541f, 0.28329173f, -0.036314f, -0.02618981f }
#define TCONST { 0.7052508f, 0.35964987f, 0.10623224f, -0.04634768f, \
                 0.8112458f, -0.24774243f, -0.44142142f, -1.3476763f, \
                 -0.4575439f, -1.9938357f, 0.99998903f, 0.99853265f,  \
                 0.82849f, 0.57890254f, -2.021475f, -2.7414792f }

// ---- packed f32x2 helpers (Blackwell FFMA2 path, PTX-only) ----
__device__ __forceinline__ u64 pack2(float lo, float hi) {
    u64 r;
    asm("mov.b64 %0, {%1, %2};" : "=l"(r) : "f"(lo), "f"(hi));
    return r;
}
__device__ __forceinline__ void unpack2(u64 p, float& lo, float& hi) {
    asm("mov.b64 {%0, %1}, %2;" : "=f"(lo), "=f"(hi) : "l"(p));
}
__device__ __forceinline__ u64 ffma2(u64 a, u64 b, u64 c) {
    u64 d;
    asm("fma.rn.f32x2 %0, %1, %2, %3;" : "=l"(d) : "l"(a), "l"(b), "l"(c));
    return d;
}
__device__ __forceinline__ u64 fmul2(u64 a, u64 b) {
    u64 d;
    asm("mul.rn.f32x2 %0, %1, %2;" : "=l"(d) : "l"(a), "l"(b));
    return d;
}
// set.gt -> SASS FSET.BF: 1.0f if a > b else 0.0f, single issue, no predicate.
__device__ __forceinline__ float fset_gt(float a, float b) {
    float d;
    asm("set.gt.f32.f32 %0, %1, %2;" : "=f"(d) : "f"(a), "f"(b));
    return d;
}

__global__ void __launch_bounds__(NTHREADS)
spike_f32x2_kernel(const float4* __restrict__ x, float4* __restrict__ out) {
    const float H[16] = HCONST;
    const float D[16] = DCONST;
    const float T[16] = TCONST;

    const int base = blockIdx.x * (NTHREADS * F4_PER_THREAD) + threadIdx.x;

    float vl[PAIRS], vh[PAIRS];
    u64 v2[PAIRS], o2[PAIRS], z2[PAIRS];

#pragma unroll
    for (int j = 0; j < F4_PER_THREAD; j++) {
        float4 t = __ldcs(x + base + j * NTHREADS);
        vl[2 * j]     = t.x; vh[2 * j]     = t.y;
        vl[2 * j + 1] = t.z; vh[2 * j + 1] = t.w;
        v2[2 * j]     = pack2(t.x, t.y);
        v2[2 * j + 1] = pack2(t.z, t.w);
    }

    // step 0: z starts at 0, so no v-update; o = z * d0
    {
        const u64 d2 = pack2(D[0], D[0]);
#pragma unroll
        for (int p = 0; p < PAIRS; p++) {
            float zl = fset_gt(vl[p], T[0]);
            float zh = fset_gt(vh[p], T[0]);
            z2[p] = pack2(zl, zh);
            o2[p] = fmul2(z2[p], d2);
        }
    }

#pragma unroll
    for (int k = 1; k < 16; k++) {
        const u64 nh2 = pack2(-H[k], -H[k]);
        const u64 d2  = pack2(D[k], D[k]);
#pragma unroll
        for (int p = 0; p < PAIRS; p++) {
            // v = fma(z_prev, -h, v)  — bit-identical to v - z*h for z in {0,1}
            v2[p] = ffma2(z2[p], nh2, v2[p]);
            unpack2(v2[p], vl[p], vh[p]);
            float zl = fset_gt(vl[p], T[k]);   // FSET.BF -> 1.0f / 0.0f
            float zh = fset_gt(vh[p], T[k]);
            z2[p] = pack2(zl, zh);
            // out = fma(z, d, out)
            o2[p] = ffma2(z2[p], d2, o2[p]);
        }
    }

#pragma unroll
    for (int j = 0; j < F4_PER_THREAD; j++) {
        float ox, oy, oz, ow;
        unpack2(o2[2 * j], ox, oy);
        unpack2(o2[2 * j + 1], oz, ow);
        __stcs(out + base + j * NTHREADS, make_float4(ox, oy, oz, ow));
    }
}

// Generic scalar fallback (any n); never launched for the bench shape.
__global__ void __launch_bounds__(NTHREADS)
spike_generic_kernel(const float* __restrict__ x, float* __restrict__ out, int n) {
    const float H[16] = HCONST;
    const float D[16] = DCONST;
    const float T[16] = TCONST;
    int idx = blockIdx.x * NTHREADS + threadIdx.x;
    if (idx >= n) return;
    float v = x[idx], o = 0.0f;
    bool z = false;
#pragma unroll
    for (int k = 0; k < 16; k++) {
        if (z) v -= H[k];
        z = v > T[k];
        if (z) o += D[k];
    }
    out[idx] = o;
}

extern "C" void kernel_launch(void* const* d_in, const int* in_sizes, int n_in,
                              void* d_out, int out_size) {
    const float* x = (const float*)d_in[0];
    float* out = (float*)d_out;
    int n = in_sizes[0];

    const int per_block = NTHREADS * EPT;  // elements per block
    if (n % per_block == 0) {
        int blocks = n / per_block;
        spike_f32x2_kernel<<<blocks, NTHREADS>>>((const float4*)x, (float4*)out);
    } else {
        int blocks = (n + NTHREADS - 1) / NTHREADS;
        spike_generic_kernel<<<blocks, NTHREADS>>>(x, out, n);
    }
}